// round 1
// baseline (speedup 1.0000x reference)
#include <cuda_runtime.h>
#include <cuda_bf16.h>
#include <math.h>

// ---------------- problem constants ----------------
#define VOCAB 32000
#define EMB   512
#define SEQ   2048
#define NHEAD 8
#define NLAYER 6
#define FFDIM 2048
#define BATCH 2
#define HEADD 64
#define BT    (BATCH*SEQ)      // 4096 tokens
#define EPS_LN 1e-5f

// ---------------- scratch (device globals; no allocation allowed) ----------------
__device__ float g_h [BT*EMB];     // residual stream
__device__ float g_y [BT*EMB];     // LN output
__device__ float g_q [BT*EMB];
__device__ float g_k [BT*EMB];
__device__ float g_v [BT*EMB];
__device__ float g_o [BT*EMB];     // attention output
__device__ float g_ff[BT*FFDIM];   // FFN hidden

// ---------------- embedding ----------------
__global__ void embed_kernel(const int* __restrict__ x,
                             const float* __restrict__ tok,
                             const float* __restrict__ pos,
                             float* __restrict__ h)
{
    int row = blockIdx.x;            // 0..BT-1
    int t   = row % SEQ;
    int id  = x[row];
    const float* te = tok + (size_t)id * EMB;
    const float* pe = pos + (size_t)t  * EMB;
    float* out = h + (size_t)row * EMB;
    for (int i = threadIdx.x; i < EMB; i += blockDim.x)
        out[i] = te[i] + pe[i];
}

// ---------------- layernorm (one block per token) ----------------
__global__ void ln_kernel(const float* __restrict__ X,
                          const float* __restrict__ scale,
                          const float* __restrict__ bias,
                          float* __restrict__ Y)
{
    int row = blockIdx.x;
    int t = threadIdx.x;                   // 128 threads
    const float* x = X + (size_t)row * EMB;
    float* y = Y + (size_t)row * EMB;

    float s = 0.f, sq = 0.f;
    #pragma unroll
    for (int i = t; i < EMB; i += 128) { float v = x[i]; s += v; sq += v*v; }

    __shared__ float r1[128], r2[128];
    r1[t] = s; r2[t] = sq;
    __syncthreads();
    for (int k = 64; k > 0; k >>= 1) {
        if (t < k) { r1[t] += r1[t+k]; r2[t] += r2[t+k]; }
        __syncthreads();
    }
    float mean = r1[0] * (1.0f/EMB);
    float var  = r2[0] * (1.0f/EMB) - mean*mean;
    float rstd = rsqrtf(var + EPS_LN);

    #pragma unroll
    for (int i = t; i < EMB; i += 128)
        y[i] = (x[i] - mean) * rstd * scale[i] + bias[i];
}

// ---------------- generic tiled SGEMM: C = [C +] A(MxK) @ W(KxN) + bias, opt ReLU ----------------
// BM=BN=64, BK=32, 256 threads, each thread computes 4x4.
// Requires M%64==0, N%64==0, K%32==0 (holds for all shapes here).
template<bool RELU, bool RES>
__global__ void gemm_kernel(int M, int N, int K,
                            const float* __restrict__ A,
                            const float* __restrict__ W,
                            const float* __restrict__ bias,
                            float* __restrict__ C)
{
    __shared__ float As[64][33];   // [m][k], padded
    __shared__ float Ws[32][64];   // [k][n]

    const int bx = blockIdx.x;     // N tile
    const int by = blockIdx.y;     // M tile
    const int tid = threadIdx.x;   // 0..255
    const int tx = tid & 15;       // 0..15 -> 4 cols each
    const int ty = tid >> 4;       // 0..15 -> 4 rows each

    const int aRow0 = tid >> 3;          // 0..31
    const int aCol4 = (tid & 7) << 2;    // 0,4,..,28
    const int wRow0 = tid >> 4;          // 0..15
    const int wCol4 = (tid & 15) << 2;   // 0,4,..,60

    float acc[4][4];
    #pragma unroll
    for (int i = 0; i < 4; i++)
        #pragma unroll
        for (int j = 0; j < 4; j++) acc[i][j] = 0.f;

    for (int kt = 0; kt < K; kt += 32) {
        #pragma unroll
        for (int rr = 0; rr < 2; rr++) {
            int r = aRow0 + rr*32;
            float4 v = *(const float4*)&A[(size_t)(by*64 + r)*K + kt + aCol4];
            As[r][aCol4+0] = v.x; As[r][aCol4+1] = v.y;
            As[r][aCol4+2] = v.z; As[r][aCol4+3] = v.w;
        }
        #pragma unroll
        for (int rr = 0; rr < 2; rr++) {
            int r = wRow0 + rr*16;
            *(float4*)&Ws[r][wCol4] =
                *(const float4*)&W[(size_t)(kt + r)*N + bx*64 + wCol4];
        }
        __syncthreads();

        #pragma unroll
        for (int k = 0; k < 32; k++) {
            float4 bv = *(float4*)&Ws[k][tx*4];
            float a0 = As[ty*4+0][k];
            float a1 = As[ty*4+1][k];
            float a2 = As[ty*4+2][k];
            float a3 = As[ty*4+3][k];
            acc[0][0] += a0*bv.x; acc[0][1] += a0*bv.y; acc[0][2] += a0*bv.z; acc[0][3] += a0*bv.w;
            acc[1][0] += a1*bv.x; acc[1][1] += a1*bv.y; acc[1][2] += a1*bv.z; acc[1][3] += a1*bv.w;
            acc[2][0] += a2*bv.x; acc[2][1] += a2*bv.y; acc[2][2] += a2*bv.z; acc[2][3] += a2*bv.w;
            acc[3][0] += a3*bv.x; acc[3][1] += a3*bv.y; acc[3][2] += a3*bv.z; acc[3][3] += a3*bv.w;
        }
        __syncthreads();
    }

    float4 bv = *(const float4*)&bias[bx*64 + tx*4];
    #pragma unroll
    for (int i = 0; i < 4; i++) {
        int row = by*64 + ty*4 + i;
        float4* cp = (float4*)&C[(size_t)row*N + bx*64 + tx*4];
        float4 r;
        r.x = acc[i][0] + bv.x;
        r.y = acc[i][1] + bv.y;
        r.z = acc[i][2] + bv.z;
        r.w = acc[i][3] + bv.w;
        if (RELU) {
            r.x = fmaxf(r.x, 0.f); r.y = fmaxf(r.y, 0.f);
            r.z = fmaxf(r.z, 0.f); r.w = fmaxf(r.w, 0.f);
        }
        if (RES) {
            float4 old = *cp;
            r.x += old.x; r.y += old.y; r.z += old.z; r.w += old.w;
        }
        *cp = r;
    }
}

// ---------------- causal attention: one block per (b,h,q) ----------------
__global__ void attn_kernel(const float* __restrict__ Q,
                            const float* __restrict__ K,
                            const float* __restrict__ V,
                            float* __restrict__ O)
{
    const int q = blockIdx.x;
    const int h = blockIdx.y;
    const int b = blockIdx.z;
    const int t = threadIdx.x;   // 128 threads

    __shared__ float qv[HEADD];
    __shared__ float sc[SEQ];
    __shared__ float red[128];

    const size_t base = ((size_t)b*SEQ)*EMB + h*HEADD;
    const float* qrow = Q + base + (size_t)q*EMB;
    if (t < HEADD) qv[t] = qrow[t];
    __syncthreads();

    const int nk = q + 1;

    // scores + local max
    float lmax = -1e30f;
    for (int k = t; k < nk; k += 128) {
        const float* krow = K + base + (size_t)k*EMB;
        float d = 0.f;
        #pragma unroll
        for (int j = 0; j < HEADD; j++) d += qv[j]*krow[j];
        d *= 0.125f;                    // 1/sqrt(64)
        sc[k] = d;
        lmax = fmaxf(lmax, d);
    }
    red[t] = lmax;
    __syncthreads();
    for (int s = 64; s > 0; s >>= 1) {
        if (t < s) red[t] = fmaxf(red[t], red[t+s]);
        __syncthreads();
    }
    const float m = red[0];
    __syncthreads();

    // exp + local sum
    float lsum = 0.f;
    for (int k = t; k < nk; k += 128) {
        float e = __expf(sc[k] - m);
        sc[k] = e;
        lsum += e;
    }
    red[t] = lsum;
    __syncthreads();
    for (int s = 64; s > 0; s >>= 1) {
        if (t < s) red[t] += red[t+s];
        __syncthreads();
    }
    const float inv = 1.0f / red[0];
    __syncthreads();

    // output: 2 threads per dim (split keys), combine
    const int d    = t & 63;
    const int half = t >> 6;
    float acc = 0.f;
    for (int k = half; k < nk; k += 2)
        acc += sc[k] * V[base + (size_t)k*EMB + d];
    red[t] = acc;
    __syncthreads();
    if (t < HEADD)
        O[base + (size_t)q*EMB + t] = (red[t] + red[t+64]) * inv;
}

// ---------------- orchestration ----------------
extern "C" void kernel_launch(void* const* d_in, const int* in_sizes, int n_in,
                              void* d_out, int out_size)
{
    (void)in_sizes; (void)n_in;
    const int*   x       = (const int*)  d_in[0];
    const float* tok_emb = (const float*)d_in[1];
    const float* pos_emb = (const float*)d_in[2];
    const float* Wq   = (const float*)d_in[3];
    const float* bq   = (const float*)d_in[4];
    const float* Wk   = (const float*)d_in[5];
    const float* bk   = (const float*)d_in[6];
    const float* Wv   = (const float*)d_in[7];
    const float* bv   = (const float*)d_in[8];
    const float* Wo   = (const float*)d_in[9];
    const float* bo   = (const float*)d_in[10];
    const float* ln1s = (const float*)d_in[11];
    const float* ln1b = (const float*)d_in[12];
    const float* ln2s = (const float*)d_in[13];
    const float* ln2b = (const float*)d_in[14];
    const float* W1   = (const float*)d_in[15];
    const float* b1   = (const float*)d_in[16];
    const float* W2   = (const float*)d_in[17];
    const float* b2   = (const float*)d_in[18];
    const float* Wout = (const float*)d_in[19];
    const float* bout = (const float*)d_in[20];
    float* out = (float*)d_out;
    (void)out_size;

    float *h, *y, *q, *k, *v, *o, *ff;
    cudaGetSymbolAddress((void**)&h,  g_h);
    cudaGetSymbolAddress((void**)&y,  g_y);
    cudaGetSymbolAddress((void**)&q,  g_q);
    cudaGetSymbolAddress((void**)&k,  g_k);
    cudaGetSymbolAddress((void**)&v,  g_v);
    cudaGetSymbolAddress((void**)&o,  g_o);
    cudaGetSymbolAddress((void**)&ff, g_ff);

    const int M = BT;
    embed_kernel<<<BT, 128>>>(x, tok_emb, pos_emb, h);

    for (int i = 0; i < NLAYER; i++) {
        const float* Wqi = Wq + (size_t)i*EMB*EMB;
        const float* Wki = Wk + (size_t)i*EMB*EMB;
        const float* Wvi = Wv + (size_t)i*EMB*EMB;
        const float* Woi = Wo + (size_t)i*EMB*EMB;
        const float* W1i = W1 + (size_t)i*EMB*FFDIM;
        const float* W2i = W2 + (size_t)i*FFDIM*EMB;

        ln_kernel<<<BT, 128>>>(h, ln1s + i*EMB, ln1b + i*EMB, y);

        dim3 gE(EMB/64, M/64);
        gemm_kernel<false,false><<<gE, 256>>>(M, EMB, EMB, y, Wqi, bq + i*EMB, q);
        gemm_kernel<false,false><<<gE, 256>>>(M, EMB, EMB, y, Wki, bk + i*EMB, k);
        gemm_kernel<false,false><<<gE, 256>>>(M, EMB, EMB, y, Wvi, bv + i*EMB, v);

        attn_kernel<<<dim3(SEQ, NHEAD, BATCH), 128>>>(q, k, v, o);

        gemm_kernel<false,true><<<gE, 256>>>(M, EMB, EMB, o, Woi, bo + i*EMB, h);

        ln_kernel<<<BT, 128>>>(h, ln2s + i*EMB, ln2b + i*EMB, y);

        dim3 gF1(FFDIM/64, M/64);
        gemm_kernel<true,false><<<gF1, 256>>>(M, FFDIM, EMB, y, W1i, b1 + i*FFDIM, ff);

        dim3 gF2(EMB/64, M/64);
        gemm_kernel<false,true><<<gF2, 256>>>(M, EMB, FFDIM, ff, W2i, b2 + i*EMB, h);
    }

    dim3 gO(VOCAB/64, M/64);
    gemm_kernel<false,false><<<gO, 256>>>(M, VOCAB, EMB, h, Wout, bout, out);
}

// round 2
// speedup vs baseline: 4.9638x; 4.9638x over previous
#include <cuda_runtime.h>
#include <cuda_bf16.h>
#include <math.h>

// ---------------- problem constants ----------------
#define VOCAB 32000
#define EMB   512
#define SEQ   2048
#define NHEAD 8
#define NLAYER 6
#define FFDIM 2048
#define BATCH 2
#define HEADD 64
#define BT    (BATCH*SEQ)      // 4096 tokens
#define EPS_LN 1e-5f

// ---------------- scratch (device globals; no allocation allowed) ----------------
__device__ float g_h [BT*EMB];     // residual stream
__device__ float g_y [BT*EMB];     // LN output
__device__ float g_q [BT*EMB];
__device__ float g_k [BT*EMB];
__device__ float g_v [BT*EMB];
__device__ float g_o [BT*EMB];     // attention output
__device__ float g_ff[BT*FFDIM];   // FFN hidden

// ---------------- embedding ----------------
__global__ void embed_kernel(const int* __restrict__ x,
                             const float* __restrict__ tok,
                             const float* __restrict__ pos,
                             float* __restrict__ h)
{
    int row = blockIdx.x;            // 0..BT-1
    int t   = row % SEQ;
    int id  = x[row];
    const float* te = tok + (size_t)id * EMB;
    const float* pe = pos + (size_t)t  * EMB;
    float* out = h + (size_t)row * EMB;
    for (int i = threadIdx.x; i < EMB; i += blockDim.x)
        out[i] = te[i] + pe[i];
}

// ---------------- layernorm (one block per token) ----------------
__global__ void ln_kernel(const float* __restrict__ X,
                          const float* __restrict__ scale,
                          const float* __restrict__ bias,
                          float* __restrict__ Y)
{
    int row = blockIdx.x;
    int t = threadIdx.x;                   // 128 threads
    const float* x = X + (size_t)row * EMB;
    float* y = Y + (size_t)row * EMB;

    float s = 0.f, sq = 0.f;
    #pragma unroll
    for (int i = t; i < EMB; i += 128) { float v = x[i]; s += v; sq += v*v; }

    __shared__ float r1[128], r2[128];
    r1[t] = s; r2[t] = sq;
    __syncthreads();
    for (int k = 64; k > 0; k >>= 1) {
        if (t < k) { r1[t] += r1[t+k]; r2[t] += r2[t+k]; }
        __syncthreads();
    }
    float mean = r1[0] * (1.0f/EMB);
    float var  = r2[0] * (1.0f/EMB) - mean*mean;
    float rstd = rsqrtf(var + EPS_LN);

    #pragma unroll
    for (int i = t; i < EMB; i += 128)
        y[i] = (x[i] - mean) * rstd * scale[i] + bias[i];
}

// ---------------- generic tiled SGEMM (unchanged, known-good) ----------------
template<bool RELU, bool RES>
__global__ void gemm_kernel(int M, int N, int K,
                            const float* __restrict__ A,
                            const float* __restrict__ W,
                            const float* __restrict__ bias,
                            float* __restrict__ C)
{
    __shared__ float As[64][33];   // [m][k], padded
    __shared__ float Ws[32][64];   // [k][n]

    const int bx = blockIdx.x;     // N tile
    const int by = blockIdx.y;     // M tile
    const int tid = threadIdx.x;   // 0..255
    const int tx = tid & 15;       // 0..15 -> 4 cols each
    const int ty = tid >> 4;       // 0..15 -> 4 rows each

    const int aRow0 = tid >> 3;          // 0..31
    const int aCol4 = (tid & 7) << 2;    // 0,4,..,28
    const int wRow0 = tid >> 4;          // 0..15
    const int wCol4 = (tid & 15) << 2;   // 0,4,..,60

    float acc[4][4];
    #pragma unroll
    for (int i = 0; i < 4; i++)
        #pragma unroll
        for (int j = 0; j < 4; j++) acc[i][j] = 0.f;

    for (int kt = 0; kt < K; kt += 32) {
        #pragma unroll
        for (int rr = 0; rr < 2; rr++) {
            int r = aRow0 + rr*32;
            float4 v = *(const float4*)&A[(size_t)(by*64 + r)*K + kt + aCol4];
            As[r][aCol4+0] = v.x; As[r][aCol4+1] = v.y;
            As[r][aCol4+2] = v.z; As[r][aCol4+3] = v.w;
        }
        #pragma unroll
        for (int rr = 0; rr < 2; rr++) {
            int r = wRow0 + rr*16;
            *(float4*)&Ws[r][wCol4] =
                *(const float4*)&W[(size_t)(kt + r)*N + bx*64 + wCol4];
        }
        __syncthreads();

        #pragma unroll
        for (int k = 0; k < 32; k++) {
            float4 bv = *(float4*)&Ws[k][tx*4];
            float a0 = As[ty*4+0][k];
            float a1 = As[ty*4+1][k];
            float a2 = As[ty*4+2][k];
            float a3 = As[ty*4+3][k];
            acc[0][0] += a0*bv.x; acc[0][1] += a0*bv.y; acc[0][2] += a0*bv.z; acc[0][3] += a0*bv.w;
            acc[1][0] += a1*bv.x; acc[1][1] += a1*bv.y; acc[1][2] += a1*bv.z; acc[1][3] += a1*bv.w;
            acc[2][0] += a2*bv.x; acc[2][1] += a2*bv.y; acc[2][2] += a2*bv.z; acc[2][3] += a2*bv.w;
            acc[3][0] += a3*bv.x; acc[3][1] += a3*bv.y; acc[3][2] += a3*bv.z; acc[3][3] += a3*bv.w;
        }
        __syncthreads();
    }

    float4 bv = *(const float4*)&bias[bx*64 + tx*4];
    #pragma unroll
    for (int i = 0; i < 4; i++) {
        int row = by*64 + ty*4 + i;
        float4* cp = (float4*)&C[(size_t)row*N + bx*64 + tx*4];
        float4 r;
        r.x = acc[i][0] + bv.x;
        r.y = acc[i][1] + bv.y;
        r.z = acc[i][2] + bv.z;
        r.w = acc[i][3] + bv.w;
        if (RELU) {
            r.x = fmaxf(r.x, 0.f); r.y = fmaxf(r.y, 0.f);
            r.z = fmaxf(r.z, 0.f); r.w = fmaxf(r.w, 0.f);
        }
        if (RES) {
            float4 old = *cp;
            r.x += old.x; r.y += old.y; r.z += old.z; r.w += old.w;
        }
        *cp = r;
    }
}

// ---------------- flash attention: 64 queries per CTA, 32-key tiles ----------------
// grid (SEQ/64, NHEAD, BATCH), 128 threads. ty=tid>>3 (0..15, 4 q-rows each),
// tx=tid&7 (0..7, 4 key-cols / 8 out-dims each).
__global__ __launch_bounds__(128) void attn_flash_kernel(
        const float* __restrict__ Q,
        const float* __restrict__ K,
        const float* __restrict__ V,
        float* __restrict__ O)
{
    const int qt = blockIdx.x;
    const int h  = blockIdx.y;
    const int b  = blockIdx.z;
    const int tid = threadIdx.x;
    const int ty = tid >> 3;     // 0..15
    const int tx = tid & 7;      // 0..7

    __shared__ float Qs[64][68];   // [d][q]  (transposed, pre-scaled)
    __shared__ float Ks[64][36];   // [d][k]  (transposed)
    __shared__ float Vs[32][68];   // [k][d]
    __shared__ float Ps[64][36];   // [q][k]

    const size_t base = ((size_t)b*SEQ)*EMB + (size_t)h*HEADD;

    // ---- load Q tile (transposed into smem, pre-scaled by 1/sqrt(64)) ----
    for (int idx = tid; idx < 64*16; idx += 128) {
        int q  = idx >> 4;
        int d4 = (idx & 15) << 2;
        float4 v = *(const float4*)&Q[base + (size_t)(qt*64 + q)*EMB + d4];
        Qs[d4+0][q] = v.x * 0.125f;
        Qs[d4+1][q] = v.y * 0.125f;
        Qs[d4+2][q] = v.z * 0.125f;
        Qs[d4+3][q] = v.w * 0.125f;
    }

    float m[4], l[4], o[4][8];
    #pragma unroll
    for (int i = 0; i < 4; i++) {
        m[i] = -1e30f; l[i] = 0.f;
        #pragma unroll
        for (int j = 0; j < 8; j++) o[i][j] = 0.f;
    }

    const int nkt = 2*qt + 2;
    for (int kt = 0; kt < nkt; kt++) {
        __syncthreads();   // protect Ks/Vs/Ps from previous iteration readers (and Qs stores, kt=0)

        // ---- load K tile (transposed) and V tile, coalesced ----
        for (int idx = tid; idx < 32*16; idx += 128) {
            int k  = idx >> 4;
            int d4 = (idx & 15) << 2;
            float4 kv = *(const float4*)&K[base + (size_t)(kt*32 + k)*EMB + d4];
            Ks[d4+0][k] = kv.x; Ks[d4+1][k] = kv.y;
            Ks[d4+2][k] = kv.z; Ks[d4+3][k] = kv.w;
            *(float4*)&Vs[k][d4] =
                *(const float4*)&V[base + (size_t)(kt*32 + k)*EMB + d4];
        }
        __syncthreads();

        // ---- scores: acc[i][j] = sum_d Qs[d][4ty+i] * Ks[d][4tx+j] ----
        float acc[4][4];
        #pragma unroll
        for (int i = 0; i < 4; i++)
            #pragma unroll
            for (int j = 0; j < 4; j++) acc[i][j] = 0.f;

        #pragma unroll 8
        for (int d = 0; d < 64; d++) {
            float4 qv = *(const float4*)&Qs[d][ty*4];
            float4 kv = *(const float4*)&Ks[d][tx*4];
            acc[0][0] += qv.x*kv.x; acc[0][1] += qv.x*kv.y; acc[0][2] += qv.x*kv.z; acc[0][3] += qv.x*kv.w;
            acc[1][0] += qv.y*kv.x; acc[1][1] += qv.y*kv.y; acc[1][2] += qv.y*kv.z; acc[1][3] += qv.y*kv.w;
            acc[2][0] += qv.z*kv.x; acc[2][1] += qv.z*kv.y; acc[2][2] += qv.z*kv.z; acc[2][3] += qv.z*kv.w;
            acc[3][0] += qv.w*kv.x; acc[3][1] += qv.w*kv.y; acc[3][2] += qv.w*kv.z; acc[3][3] += qv.w*kv.w;
        }

        // ---- causal mask (only the last two key tiles can cross the diagonal) ----
        if (kt >= 2*qt) {
            #pragma unroll
            for (int i = 0; i < 4; i++) {
                int qg = qt*64 + ty*4 + i;
                #pragma unroll
                for (int j = 0; j < 4; j++) {
                    int kg = kt*32 + tx*4 + j;
                    if (kg > qg) acc[i][j] = -1e30f;
                }
            }
        }

        // ---- online softmax update (row groups = 8 lanes sharing ty) ----
        #pragma unroll
        for (int i = 0; i < 4; i++) {
            float rmax = fmaxf(fmaxf(acc[i][0], acc[i][1]), fmaxf(acc[i][2], acc[i][3]));
            rmax = fmaxf(rmax, __shfl_xor_sync(0xffffffffu, rmax, 1));
            rmax = fmaxf(rmax, __shfl_xor_sync(0xffffffffu, rmax, 2));
            rmax = fmaxf(rmax, __shfl_xor_sync(0xffffffffu, rmax, 4));
            float mn = fmaxf(m[i], rmax);
            float c  = __expf(m[i] - mn);
            m[i] = mn;
            l[i] *= c;
            #pragma unroll
            for (int j = 0; j < 8; j++) o[i][j] *= c;
            float ps = 0.f;
            #pragma unroll
            for (int j = 0; j < 4; j++) {
                float p = __expf(acc[i][j] - mn);
                Ps[ty*4+i][tx*4+j] = p;
                ps += p;
            }
            ps += __shfl_xor_sync(0xffffffffu, ps, 1);
            ps += __shfl_xor_sync(0xffffffffu, ps, 2);
            ps += __shfl_xor_sync(0xffffffffu, ps, 4);
            l[i] += ps;
        }
        __syncthreads();

        // ---- PV: o[i][*] += sum_k Ps[4ty+i][k] * Vs[k][tx*8 + *] ----
        for (int k = 0; k < 32; k += 4) {
            float p[4][4];
            #pragma unroll
            for (int i = 0; i < 4; i++)
                *(float4*)p[i] = *(const float4*)&Ps[ty*4+i][k];
            #pragma unroll
            for (int kk = 0; kk < 4; kk++) {
                float4 v0 = *(const float4*)&Vs[k+kk][tx*8];
                float4 v1 = *(const float4*)&Vs[k+kk][tx*8+4];
                #pragma unroll
                for (int i = 0; i < 4; i++) {
                    float pv = p[i][kk];
                    o[i][0] += pv*v0.x; o[i][1] += pv*v0.y;
                    o[i][2] += pv*v0.z; o[i][3] += pv*v0.w;
                    o[i][4] += pv*v1.x; o[i][5] += pv*v1.y;
                    o[i][6] += pv*v1.z; o[i][7] += pv*v1.w;
                }
            }
        }
    }

    // ---- epilogue: normalize and store ----
    #pragma unroll
    for (int i = 0; i < 4; i++) {
        float inv = 1.0f / l[i];
        int qg = qt*64 + ty*4 + i;
        float4 r0, r1;
        r0.x = o[i][0]*inv; r0.y = o[i][1]*inv; r0.z = o[i][2]*inv; r0.w = o[i][3]*inv;
        r1.x = o[i][4]*inv; r1.y = o[i][5]*inv; r1.z = o[i][6]*inv; r1.w = o[i][7]*inv;
        float* op = &O[base + (size_t)qg*EMB + tx*8];
        *(float4*)op       = r0;
        *(float4*)(op + 4) = r1;
    }
}

// ---------------- orchestration ----------------
extern "C" void kernel_launch(void* const* d_in, const int* in_sizes, int n_in,
                              void* d_out, int out_size)
{
    (void)in_sizes; (void)n_in;
    const int*   x       = (const int*)  d_in[0];
    const float* tok_emb = (const float*)d_in[1];
    const float* pos_emb = (const float*)d_in[2];
    const float* Wq   = (const float*)d_in[3];
    const float* bq   = (const float*)d_in[4];
    const float* Wk   = (const float*)d_in[5];
    const float* bk   = (const float*)d_in[6];
    const float* Wv   = (const float*)d_in[7];
    const float* bv   = (const float*)d_in[8];
    const float* Wo   = (const float*)d_in[9];
    const float* bo   = (const float*)d_in[10];
    const float* ln1s = (const float*)d_in[11];
    const float* ln1b = (const float*)d_in[12];
    const float* ln2s = (const float*)d_in[13];
    const float* ln2b = (const float*)d_in[14];
    const float* W1   = (const float*)d_in[15];
    const float* b1   = (const float*)d_in[16];
    const float* W2   = (const float*)d_in[17];
    const float* b2   = (const float*)d_in[18];
    const float* Wout = (const float*)d_in[19];
    const float* bout = (const float*)d_in[20];
    float* out = (float*)d_out;
    (void)out_size;

    float *h, *y, *q, *k, *v, *o, *ff;
    cudaGetSymbolAddress((void**)&h,  g_h);
    cudaGetSymbolAddress((void**)&y,  g_y);
    cudaGetSymbolAddress((void**)&q,  g_q);
    cudaGetSymbolAddress((void**)&k,  g_k);
    cudaGetSymbolAddress((void**)&v,  g_v);
    cudaGetSymbolAddress((void**)&o,  g_o);
    cudaGetSymbolAddress((void**)&ff, g_ff);

    const int M = BT;
    embed_kernel<<<BT, 128>>>(x, tok_emb, pos_emb, h);

    for (int i = 0; i < NLAYER; i++) {
        const float* Wqi = Wq + (size_t)i*EMB*EMB;
        const float* Wki = Wk + (size_t)i*EMB*EMB;
        const float* Wvi = Wv + (size_t)i*EMB*EMB;
        const float* Woi = Wo + (size_t)i*EMB*EMB;
        const float* W1i = W1 + (size_t)i*EMB*FFDIM;
        const float* W2i = W2 + (size_t)i*FFDIM*EMB;

        ln_kernel<<<BT, 128>>>(h, ln1s + i*EMB, ln1b + i*EMB, y);

        dim3 gE(EMB/64, M/64);
        gemm_kernel<false,false><<<gE, 256>>>(M, EMB, EMB, y, Wqi, bq + i*EMB, q);
        gemm_kernel<false,false><<<gE, 256>>>(M, EMB, EMB, y, Wki, bk + i*EMB, k);
        gemm_kernel<false,false><<<gE, 256>>>(M, EMB, EMB, y, Wvi, bv + i*EMB, v);

        attn_flash_kernel<<<dim3(SEQ/64, NHEAD, BATCH), 128>>>(q, k, v, o);

        gemm_kernel<false,true><<<gE, 256>>>(M, EMB, EMB, o, Woi, bo + i*EMB, h);

        ln_kernel<<<BT, 128>>>(h, ln2s + i*EMB, ln2b + i*EMB, y);

        dim3 gF1(FFDIM/64, M/64);
        gemm_kernel<true,false><<<gF1, 256>>>(M, FFDIM, EMB, y, W1i, b1 + i*FFDIM, ff);

        dim3 gF2(EMB/64, M/64);
        gemm_kernel<false,true><<<gF2, 256>>>(M, EMB, FFDIM, ff, W2i, b2 + i*EMB, h);
    }

    dim3 gO(VOCAB/64, M/64);
    gemm_kernel<false,false><<<gO, 256>>>(M, VOCAB, EMB, h, Wout, bout, out);
}

// round 3
// speedup vs baseline: 8.7608x; 1.7649x over previous
#include <cuda_runtime.h>
#include <cuda_bf16.h>
#include <math.h>
#include <stdint.h>

// ---------------- problem constants ----------------
#define VOCAB 32000
#define EMB   512
#define SEQ   2048
#define NHEAD 8
#define NLAYER 6
#define FFDIM 2048
#define BATCH 2
#define HEADD 64
#define BT    (BATCH*SEQ)      // 4096 tokens
#define EPS_LN 1e-5f

// ---------------- scratch (device globals; no allocation allowed) ----------------
__device__ float g_h [BT*EMB];
__device__ float g_y [BT*EMB];
__device__ float g_q [BT*EMB];
__device__ float g_k [BT*EMB];
__device__ float g_v [BT*EMB];
__device__ float g_o [BT*EMB];
__device__ float g_ff[BT*FFDIM];

// ---------------- embedding ----------------
__global__ void embed_kernel(const int* __restrict__ x,
                             const float* __restrict__ tok,
                             const float* __restrict__ pos,
                             float* __restrict__ h)
{
    int row = blockIdx.x;
    int t   = row % SEQ;
    int id  = x[row];
    const float* te = tok + (size_t)id * EMB;
    const float* pe = pos + (size_t)t  * EMB;
    float* out = h + (size_t)row * EMB;
    for (int i = threadIdx.x; i < EMB; i += blockDim.x)
        out[i] = te[i] + pe[i];
}

// ---------------- layernorm ----------------
__global__ void ln_kernel(const float* __restrict__ X,
                          const float* __restrict__ scale,
                          const float* __restrict__ bias,
                          float* __restrict__ Y)
{
    int row = blockIdx.x;
    int t = threadIdx.x;                   // 128 threads
    const float* x = X + (size_t)row * EMB;
    float* y = Y + (size_t)row * EMB;

    float s = 0.f, sq = 0.f;
    #pragma unroll
    for (int i = t; i < EMB; i += 128) { float v = x[i]; s += v; sq += v*v; }

    __shared__ float r1[128], r2[128];
    r1[t] = s; r2[t] = sq;
    __syncthreads();
    for (int k = 64; k > 0; k >>= 1) {
        if (t < k) { r1[t] += r1[t+k]; r2[t] += r2[t+k]; }
        __syncthreads();
    }
    float mean = r1[0] * (1.0f/EMB);
    float var  = r2[0] * (1.0f/EMB) - mean*mean;
    float rstd = rsqrtf(var + EPS_LN);

    #pragma unroll
    for (int i = t; i < EMB; i += 128)
        y[i] = (x[i] - mean) * rstd * scale[i] + bias[i];
}

// ---------------- tf32 helpers ----------------
__device__ __forceinline__ uint32_t f2tf(float f) {
    uint32_t u; asm("cvt.rna.tf32.f32 %0, %1;" : "=r"(u) : "f"(f)); return u;
}

__device__ __forceinline__ void mma_tf32(float* c, const uint32_t* a, const uint32_t* b) {
    asm volatile(
        "mma.sync.aligned.m16n8k8.row.col.f32.tf32.tf32.f32 "
        "{%0,%1,%2,%3}, {%4,%5,%6,%7}, {%8,%9}, {%0,%1,%2,%3};\n"
        : "+f"(c[0]), "+f"(c[1]), "+f"(c[2]), "+f"(c[3])
        : "r"(a[0]), "r"(a[1]), "r"(a[2]), "r"(a[3]),
          "r"(b[0]), "r"(b[1]));
}

// ---------------- tf32 tensor-core GEMM ----------------
// C[M,N] = [C +] A[M,K] @ W[K,N] + bias, opt ReLU.
// BM=128, BN=64, BK=32. 256 threads = 8 warps (4 along M x 2 along N),
// warp tile 32x32 = 2x4 m16n8k8 mma tiles. Double-buffered smem, tf32
// conversion done once at the global->smem stage.
// Requires M%128==0, N%64==0, K%32==0.
#define APAD 36   // word stride of As row  -> frag banks (4m+k)%32 all distinct
#define WPAD 68   // word stride of Ws row  -> frag banks (4k+n)%32 all distinct
#define GEMM_SMEM_BYTES ((2*128*APAD + 2*32*WPAD)*4)

template<bool RELU, bool RES>
__global__ __launch_bounds__(256) void gemm_tf32(
    int M, int N, int K,
    const float* __restrict__ A,
    const float* __restrict__ W,
    const float* __restrict__ bias,
    float* __restrict__ C)
{
    extern __shared__ uint32_t dsm[];
    uint32_t (*As)[128][APAD] = (uint32_t(*)[128][APAD])dsm;
    uint32_t (*Ws)[32][WPAD]  = (uint32_t(*)[32][WPAD])(dsm + 2*128*APAD);

    const int tid  = threadIdx.x;
    const int bx   = blockIdx.x, by = blockIdx.y;
    const int warp = tid >> 5, lane = tid & 31;
    const int m0   = (warp & 3) * 32;       // warp row offset in tile
    const int n0   = (warp >> 2) * 32;      // warp col offset in tile
    const int group = lane >> 2, tcol = lane & 3;

    // global staging indices
    const int aRow = tid >> 3;              // 0..31 (+32*i)
    const int aCol = (tid & 7) << 2;        // 0..28
    const int wRow = tid >> 4;              // 0..15 (+16*i)
    const int wCol = (tid & 15) << 2;       // 0..60

    float c[2][4][4];
    #pragma unroll
    for (int mt = 0; mt < 2; mt++)
        #pragma unroll
        for (int nt = 0; nt < 4; nt++)
            #pragma unroll
            for (int j = 0; j < 4; j++) c[mt][nt][j] = 0.f;

    const int ktiles = K >> 5;
    float4 pa[4], pw[2];

    // ---- prologue: load k-tile 0 ----
    #pragma unroll
    for (int i = 0; i < 4; i++)
        pa[i] = *(const float4*)&A[(size_t)(by*128 + aRow + i*32)*K + aCol];
    #pragma unroll
    for (int i = 0; i < 2; i++)
        pw[i] = *(const float4*)&W[(size_t)(wRow + i*16)*N + bx*64 + wCol];

    #pragma unroll
    for (int i = 0; i < 4; i++) {
        uint32_t* p = &As[0][aRow + i*32][aCol];
        p[0]=f2tf(pa[i].x); p[1]=f2tf(pa[i].y); p[2]=f2tf(pa[i].z); p[3]=f2tf(pa[i].w);
    }
    #pragma unroll
    for (int i = 0; i < 2; i++) {
        uint32_t* p = &Ws[0][wRow + i*16][wCol];
        p[0]=f2tf(pw[i].x); p[1]=f2tf(pw[i].y); p[2]=f2tf(pw[i].z); p[3]=f2tf(pw[i].w);
    }

    int s = 0;
    for (int kt = 0; kt < ktiles; kt++) {
        __syncthreads();

        // prefetch next k-tile into registers
        const bool more = (kt + 1 < ktiles);
        if (more) {
            const int kb = (kt + 1) << 5;
            #pragma unroll
            for (int i = 0; i < 4; i++)
                pa[i] = *(const float4*)&A[(size_t)(by*128 + aRow + i*32)*K + kb + aCol];
            #pragma unroll
            for (int i = 0; i < 2; i++)
                pw[i] = *(const float4*)&W[(size_t)(kb + wRow + i*16)*N + bx*64 + wCol];
        }

        // ---- compute from stage s ----
        #pragma unroll
        for (int ks = 0; ks < 4; ks++) {
            const int k0 = ks << 3;
            uint32_t af[2][4], bf[4][2];
            #pragma unroll
            for (int mt = 0; mt < 2; mt++) {
                const int mb = m0 + mt*16 + group;
                af[mt][0] = As[s][mb    ][k0 + tcol];
                af[mt][1] = As[s][mb + 8][k0 + tcol];
                af[mt][2] = As[s][mb    ][k0 + tcol + 4];
                af[mt][3] = As[s][mb + 8][k0 + tcol + 4];
            }
            #pragma unroll
            for (int nt = 0; nt < 4; nt++) {
                const int nb = n0 + nt*8 + group;
                bf[nt][0] = Ws[s][k0 + tcol    ][nb];
                bf[nt][1] = Ws[s][k0 + tcol + 4][nb];
            }
            #pragma unroll
            for (int mt = 0; mt < 2; mt++)
                #pragma unroll
                for (int nt = 0; nt < 4; nt++)
                    mma_tf32(c[mt][nt], af[mt], bf[nt]);
        }

        // ---- stage next tile ----
        if (more) {
            const int s2 = s ^ 1;
            #pragma unroll
            for (int i = 0; i < 4; i++) {
                uint32_t* p = &As[s2][aRow + i*32][aCol];
                p[0]=f2tf(pa[i].x); p[1]=f2tf(pa[i].y); p[2]=f2tf(pa[i].z); p[3]=f2tf(pa[i].w);
            }
            #pragma unroll
            for (int i = 0; i < 2; i++) {
                uint32_t* p = &Ws[s2][wRow + i*16][wCol];
                p[0]=f2tf(pw[i].x); p[1]=f2tf(pw[i].y); p[2]=f2tf(pw[i].z); p[3]=f2tf(pw[i].w);
            }
        }
        s ^= 1;
    }

    // ---- epilogue ----
    #pragma unroll
    for (int mt = 0; mt < 2; mt++) {
        #pragma unroll
        for (int nt = 0; nt < 4; nt++) {
            const int col = bx*64 + n0 + nt*8 + tcol*2;
            float2 bb = *(const float2*)&bias[col];
            #pragma unroll
            for (int r = 0; r < 2; r++) {
                const int row = by*128 + m0 + mt*16 + group + r*8;
                float2 v;
                v.x = c[mt][nt][r*2+0] + bb.x;
                v.y = c[mt][nt][r*2+1] + bb.y;
                if (RELU) { v.x = fmaxf(v.x, 0.f); v.y = fmaxf(v.y, 0.f); }
                float2* cp = (float2*)&C[(size_t)row*N + col];
                if (RES) { float2 o = *cp; v.x += o.x; v.y += o.y; }
                *cp = v;
            }
        }
    }
}

// ---------------- flash attention (unchanged, known-good) ----------------
__global__ __launch_bounds__(128) void attn_flash_kernel(
        const float* __restrict__ Q,
        const float* __restrict__ K,
        const float* __restrict__ V,
        float* __restrict__ O)
{
    const int qt = blockIdx.x;
    const int h  = blockIdx.y;
    const int b  = blockIdx.z;
    const int tid = threadIdx.x;
    const int ty = tid >> 3;     // 0..15
    const int tx = tid & 7;      // 0..7

    __shared__ float Qs[64][68];
    __shared__ float Ks[64][36];
    __shared__ float Vs[32][68];
    __shared__ float Ps[64][36];

    const size_t base = ((size_t)b*SEQ)*EMB + (size_t)h*HEADD;

    for (int idx = tid; idx < 64*16; idx += 128) {
        int q  = idx >> 4;
        int d4 = (idx & 15) << 2;
        float4 v = *(const float4*)&Q[base + (size_t)(qt*64 + q)*EMB + d4];
        Qs[d4+0][q] = v.x * 0.125f;
        Qs[d4+1][q] = v.y * 0.125f;
        Qs[d4+2][q] = v.z * 0.125f;
        Qs[d4+3][q] = v.w * 0.125f;
    }

    float m[4], l[4], o[4][8];
    #pragma unroll
    for (int i = 0; i < 4; i++) {
        m[i] = -1e30f; l[i] = 0.f;
        #pragma unroll
        for (int j = 0; j < 8; j++) o[i][j] = 0.f;
    }

    const int nkt = 2*qt + 2;
    for (int kt = 0; kt < nkt; kt++) {
        __syncthreads();

        for (int idx = tid; idx < 32*16; idx += 128) {
            int k  = idx >> 4;
            int d4 = (idx & 15) << 2;
            float4 kv = *(const float4*)&K[base + (size_t)(kt*32 + k)*EMB + d4];
            Ks[d4+0][k] = kv.x; Ks[d4+1][k] = kv.y;
            Ks[d4+2][k] = kv.z; Ks[d4+3][k] = kv.w;
            *(float4*)&Vs[k][d4] =
                *(const float4*)&V[base + (size_t)(kt*32 + k)*EMB + d4];
        }
        __syncthreads();

        float acc[4][4];
        #pragma unroll
        for (int i = 0; i < 4; i++)
            #pragma unroll
            for (int j = 0; j < 4; j++) acc[i][j] = 0.f;

        #pragma unroll 8
        for (int d = 0; d < 64; d++) {
            float4 qv = *(const float4*)&Qs[d][ty*4];
            float4 kv = *(const float4*)&Ks[d][tx*4];
            acc[0][0] += qv.x*kv.x; acc[0][1] += qv.x*kv.y; acc[0][2] += qv.x*kv.z; acc[0][3] += qv.x*kv.w;
            acc[1][0] += qv.y*kv.x; acc[1][1] += qv.y*kv.y; acc[1][2] += qv.y*kv.z; acc[1][3] += qv.y*kv.w;
            acc[2][0] += qv.z*kv.x; acc[2][1] += qv.z*kv.y; acc[2][2] += qv.z*kv.z; acc[2][3] += qv.z*kv.w;
            acc[3][0] += qv.w*kv.x; acc[3][1] += qv.w*kv.y; acc[3][2] += qv.w*kv.z; acc[3][3] += qv.w*kv.w;
        }

        if (kt >= 2*qt) {
            #pragma unroll
            for (int i = 0; i < 4; i++) {
                int qg = qt*64 + ty*4 + i;
                #pragma unroll
                for (int j = 0; j < 4; j++) {
                    int kg = kt*32 + tx*4 + j;
                    if (kg > qg) acc[i][j] = -1e30f;
                }
            }
        }

        #pragma unroll
        for (int i = 0; i < 4; i++) {
            float rmax = fmaxf(fmaxf(acc[i][0], acc[i][1]), fmaxf(acc[i][2], acc[i][3]));
            rmax = fmaxf(rmax, __shfl_xor_sync(0xffffffffu, rmax, 1));
            rmax = fmaxf(rmax, __shfl_xor_sync(0xffffffffu, rmax, 2));
            rmax = fmaxf(rmax, __shfl_xor_sync(0xffffffffu, rmax, 4));
            float mn = fmaxf(m[i], rmax);
            float cc = __expf(m[i] - mn);
            m[i] = mn;
            l[i] *= cc;
            #pragma unroll
            for (int j = 0; j < 8; j++) o[i][j] *= cc;
            float ps = 0.f;
            #pragma unroll
            for (int j = 0; j < 4; j++) {
                float p = __expf(acc[i][j] - mn);
                Ps[ty*4+i][tx*4+j] = p;
                ps += p;
            }
            ps += __shfl_xor_sync(0xffffffffu, ps, 1);
            ps += __shfl_xor_sync(0xffffffffu, ps, 2);
            ps += __shfl_xor_sync(0xffffffffu, ps, 4);
            l[i] += ps;
        }
        __syncthreads();

        for (int k = 0; k < 32; k += 4) {
            float p[4][4];
            #pragma unroll
            for (int i = 0; i < 4; i++)
                *(float4*)p[i] = *(const float4*)&Ps[ty*4+i][k];
            #pragma unroll
            for (int kk = 0; kk < 4; kk++) {
                float4 v0 = *(const float4*)&Vs[k+kk][tx*8];
                float4 v1 = *(const float4*)&Vs[k+kk][tx*8+4];
                #pragma unroll
                for (int i = 0; i < 4; i++) {
                    float pv = p[i][kk];
                    o[i][0] += pv*v0.x; o[i][1] += pv*v0.y;
                    o[i][2] += pv*v0.z; o[i][3] += pv*v0.w;
                    o[i][4] += pv*v1.x; o[i][5] += pv*v1.y;
                    o[i][6] += pv*v1.z; o[i][7] += pv*v1.w;
                }
            }
        }
    }

    #pragma unroll
    for (int i = 0; i < 4; i++) {
        float inv = 1.0f / l[i];
        int qg = qt*64 + ty*4 + i;
        float4 r0, r1;
        r0.x = o[i][0]*inv; r0.y = o[i][1]*inv; r0.z = o[i][2]*inv; r0.w = o[i][3]*inv;
        r1.x = o[i][4]*inv; r1.y = o[i][5]*inv; r1.z = o[i][6]*inv; r1.w = o[i][7]*inv;
        float* op = &O[base + (size_t)qg*EMB + tx*8];
        *(float4*)op       = r0;
        *(float4*)(op + 4) = r1;
    }
}

// ---------------- orchestration ----------------
extern "C" void kernel_launch(void* const* d_in, const int* in_sizes, int n_in,
                              void* d_out, int out_size)
{
    (void)in_sizes; (void)n_in;
    const int*   x       = (const int*)  d_in[0];
    const float* tok_emb = (const float*)d_in[1];
    const float* pos_emb = (const float*)d_in[2];
    const float* Wq   = (const float*)d_in[3];
    const float* bq   = (const float*)d_in[4];
    const float* Wk   = (const float*)d_in[5];
    const float* bk   = (const float*)d_in[6];
    const float* Wv   = (const float*)d_in[7];
    const float* bv   = (const float*)d_in[8];
    const float* Wo   = (const float*)d_in[9];
    const float* bo   = (const float*)d_in[10];
    const float* ln1s = (const float*)d_in[11];
    const float* ln1b = (const float*)d_in[12];
    const float* ln2s = (const float*)d_in[13];
    const float* ln2b = (const float*)d_in[14];
    const float* W1   = (const float*)d_in[15];
    const float* b1   = (const float*)d_in[16];
    const float* W2   = (const float*)d_in[17];
    const float* b2   = (const float*)d_in[18];
    const float* Wout = (const float*)d_in[19];
    const float* bout = (const float*)d_in[20];
    float* out = (float*)d_out;
    (void)out_size;

    float *h, *y, *q, *k, *v, *o, *ff;
    cudaGetSymbolAddress((void**)&h,  g_h);
    cudaGetSymbolAddress((void**)&y,  g_y);
    cudaGetSymbolAddress((void**)&q,  g_q);
    cudaGetSymbolAddress((void**)&k,  g_k);
    cudaGetSymbolAddress((void**)&v,  g_v);
    cudaGetSymbolAddress((void**)&o,  g_o);
    cudaGetSymbolAddress((void**)&ff, g_ff);

    // opt-in dynamic smem (idempotent; not a stream op, capture-safe)
    cudaFuncSetAttribute(gemm_tf32<false,false>,
        cudaFuncAttributeMaxDynamicSharedMemorySize, GEMM_SMEM_BYTES);
    cudaFuncSetAttribute(gemm_tf32<false,true>,
        cudaFuncAttributeMaxDynamicSharedMemorySize, GEMM_SMEM_BYTES);
    cudaFuncSetAttribute(gemm_tf32<true,false>,
        cudaFuncAttributeMaxDynamicSharedMemorySize, GEMM_SMEM_BYTES);

    const int M = BT;
    embed_kernel<<<BT, 128>>>(x, tok_emb, pos_emb, h);

    for (int i = 0; i < NLAYER; i++) {
        const float* Wqi = Wq + (size_t)i*EMB*EMB;
        const float* Wki = Wk + (size_t)i*EMB*EMB;
        const float* Wvi = Wv + (size_t)i*EMB*EMB;
        const float* Woi = Wo + (size_t)i*EMB*EMB;
        const float* W1i = W1 + (size_t)i*EMB*FFDIM;
        const float* W2i = W2 + (size_t)i*FFDIM*EMB;

        ln_kernel<<<BT, 128>>>(h, ln1s + i*EMB, ln1b + i*EMB, y);

        dim3 gE(EMB/64, M/128);
        gemm_tf32<false,false><<<gE, 256, GEMM_SMEM_BYTES>>>(M, EMB, EMB, y, Wqi, bq + i*EMB, q);
        gemm_tf32<false,false><<<gE, 256, GEMM_SMEM_BYTES>>>(M, EMB, EMB, y, Wki, bk + i*EMB, k);
        gemm_tf32<false,false><<<gE, 256, GEMM_SMEM_BYTES>>>(M, EMB, EMB, y, Wvi, bv + i*EMB, v);

        attn_flash_kernel<<<dim3(SEQ/64, NHEAD, BATCH), 128>>>(q, k, v, o);

        gemm_tf32<false,true><<<gE, 256, GEMM_SMEM_BYTES>>>(M, EMB, EMB, o, Woi, bo + i*EMB, h);

        ln_kernel<<<BT, 128>>>(h, ln2s + i*EMB, ln2b + i*EMB, y);

        dim3 gF1(FFDIM/64, M/128);
        gemm_tf32<true,false><<<gF1, 256, GEMM_SMEM_BYTES>>>(M, FFDIM, EMB, y, W1i, b1 + i*FFDIM, ff);

        dim3 gF2(EMB/64, M/128);
        gemm_tf32<false,true><<<gF2, 256, GEMM_SMEM_BYTES>>>(M, EMB, FFDIM, ff, W2i, b2 + i*EMB, h);
    }

    dim3 gO(VOCAB/64, M/128);
    gemm_tf32<false,false><<<gO, 256, GEMM_SMEM_BYTES>>>(M, VOCAB, EMB, h, Wout, bout, out);
}

// round 4
// speedup vs baseline: 9.6296x; 1.0992x over previous
#include <cuda_runtime.h>
#include <cuda_bf16.h>
#include <math.h>
#include <stdint.h>

// ---------------- problem constants ----------------
#define VOCAB 32000
#define EMB   512
#define SEQ   2048
#define NHEAD 8
#define NLAYER 6
#define FFDIM 2048
#define BATCH 2
#define HEADD 64
#define BT    (BATCH*SEQ)      // 4096 tokens
#define EPS_LN 1e-5f

// ---------------- scratch (device globals; no allocation allowed) ----------------
__device__ float g_h [BT*EMB];
__device__ float g_y [BT*EMB];
__device__ float g_q [BT*EMB];
__device__ float g_k [BT*EMB];
__device__ float g_v [BT*EMB];
__device__ float g_o [BT*EMB];
__device__ float g_ff[BT*FFDIM];

// ---------------- embedding ----------------
__global__ void embed_kernel(const int* __restrict__ x,
                             const float* __restrict__ tok,
                             const float* __restrict__ pos,
                             float* __restrict__ h)
{
    int row = blockIdx.x;
    int t   = row % SEQ;
    int id  = x[row];
    const float* te = tok + (size_t)id * EMB;
    const float* pe = pos + (size_t)t  * EMB;
    float* out = h + (size_t)row * EMB;
    for (int i = threadIdx.x; i < EMB; i += blockDim.x)
        out[i] = te[i] + pe[i];
}

// ---------------- layernorm ----------------
__global__ void ln_kernel(const float* __restrict__ X,
                          const float* __restrict__ scale,
                          const float* __restrict__ bias,
                          float* __restrict__ Y)
{
    int row = blockIdx.x;
    int t = threadIdx.x;                   // 128 threads
    const float* x = X + (size_t)row * EMB;
    float* y = Y + (size_t)row * EMB;

    float s = 0.f, sq = 0.f;
    #pragma unroll
    for (int i = t; i < EMB; i += 128) { float v = x[i]; s += v; sq += v*v; }

    __shared__ float r1[128], r2[128];
    r1[t] = s; r2[t] = sq;
    __syncthreads();
    for (int k = 64; k > 0; k >>= 1) {
        if (t < k) { r1[t] += r1[t+k]; r2[t] += r2[t+k]; }
        __syncthreads();
    }
    float mean = r1[0] * (1.0f/EMB);
    float var  = r2[0] * (1.0f/EMB) - mean*mean;
    float rstd = rsqrtf(var + EPS_LN);

    #pragma unroll
    for (int i = t; i < EMB; i += 128)
        y[i] = (x[i] - mean) * rstd * scale[i] + bias[i];
}

// ---------------- tf32 helpers ----------------
__device__ __forceinline__ uint32_t f2tf(float f) {
    uint32_t u; asm("cvt.rna.tf32.f32 %0, %1;" : "=r"(u) : "f"(f)); return u;
}

__device__ __forceinline__ void mma_tf32(float* c, const uint32_t* a, const uint32_t* b) {
    asm volatile(
        "mma.sync.aligned.m16n8k8.row.col.f32.tf32.tf32.f32 "
        "{%0,%1,%2,%3}, {%4,%5,%6,%7}, {%8,%9}, {%0,%1,%2,%3};\n"
        : "+f"(c[0]), "+f"(c[1]), "+f"(c[2]), "+f"(c[3])
        : "r"(a[0]), "r"(a[1]), "r"(a[2]), "r"(a[3]),
          "r"(b[0]), "r"(b[1]));
}

// ---------------- tf32 tensor-core GEMM core ----------------
// Block tile 128x128x32, 256 threads = 8 warps (2 along M x 4 along N),
// warp tile 64x32 = 4x4 m16n8k8 tiles = 16 MMAs per k8-step.
// Double-buffered smem; tf32 conversion once at the global->smem stage.
// Requires M%128==0, N%128==0, K%32==0.
#define APAD 36    // word stride of As row: frag banks (4*group+tcol)%32 distinct
#define WPAD 132   // word stride of Ws row: frag banks (4*tcol+group)%32 distinct
#define GEMM_SMEM_BYTES ((2*128*APAD + 2*32*WPAD)*4)   // 70656 B

template<bool RELU, bool RES>
__device__ __forceinline__ void gemm_core(
    const float* __restrict__ A,
    const float* __restrict__ W,
    const float* __restrict__ bias,
    float* __restrict__ C,
    int M, int N, int K, int bx, int by, uint32_t* dsm)
{
    uint32_t (*As)[128][APAD] = (uint32_t(*)[128][APAD])dsm;
    uint32_t (*Ws)[32][WPAD]  = (uint32_t(*)[32][WPAD])(dsm + 2*128*APAD);

    const int tid  = threadIdx.x;
    const int warp = tid >> 5, lane = tid & 31;
    const int m0   = (warp & 1) * 64;       // 2 warps along M
    const int n0   = (warp >> 1) * 32;      // 4 warps along N
    const int group = lane >> 2, tcol = lane & 3;

    // staging indices: A rows 0..127 (4 iters of 32), 8 k-float4s across
    const int aRow = tid >> 3;              // 0..31 (+32*i)
    const int aCol = (tid & 7) << 2;        // 0..28
    // W rows 0..31 (one per thread group), 4 col-chunks of 32
    const int wRow = tid >> 3;              // 0..31
    const int wCol = (tid & 7) << 2;        // 0..28 (+32*i)

    float c[4][4][4];
    #pragma unroll
    for (int mt = 0; mt < 4; mt++)
        #pragma unroll
        for (int nt = 0; nt < 4; nt++)
            #pragma unroll
            for (int j = 0; j < 4; j++) c[mt][nt][j] = 0.f;

    const int ktiles = K >> 5;
    float4 pa[4], pw[4];

    // ---- prologue: k-tile 0 ----
    #pragma unroll
    for (int i = 0; i < 4; i++)
        pa[i] = *(const float4*)&A[(size_t)(by*128 + aRow + i*32)*K + aCol];
    #pragma unroll
    for (int i = 0; i < 4; i++)
        pw[i] = *(const float4*)&W[(size_t)wRow*N + bx*128 + wCol + i*32];

    #pragma unroll
    for (int i = 0; i < 4; i++) {
        uint32_t* p = &As[0][aRow + i*32][aCol];
        p[0]=f2tf(pa[i].x); p[1]=f2tf(pa[i].y); p[2]=f2tf(pa[i].z); p[3]=f2tf(pa[i].w);
    }
    #pragma unroll
    for (int i = 0; i < 4; i++) {
        uint32_t* p = &Ws[0][wRow][wCol + i*32];
        p[0]=f2tf(pw[i].x); p[1]=f2tf(pw[i].y); p[2]=f2tf(pw[i].z); p[3]=f2tf(pw[i].w);
    }

    int s = 0;
    for (int kt = 0; kt < ktiles; kt++) {
        __syncthreads();

        const bool more = (kt + 1 < ktiles);
        if (more) {
            const int kb = (kt + 1) << 5;
            #pragma unroll
            for (int i = 0; i < 4; i++)
                pa[i] = *(const float4*)&A[(size_t)(by*128 + aRow + i*32)*K + kb + aCol];
            #pragma unroll
            for (int i = 0; i < 4; i++)
                pw[i] = *(const float4*)&W[(size_t)(kb + wRow)*N + bx*128 + wCol + i*32];
        }

        // ---- compute from stage s ----
        #pragma unroll
        for (int ks = 0; ks < 4; ks++) {
            const int k0 = ks << 3;
            uint32_t af[4][4], bf[4][2];
            #pragma unroll
            for (int mt = 0; mt < 4; mt++) {
                const int mb = m0 + mt*16 + group;
                af[mt][0] = As[s][mb    ][k0 + tcol];
                af[mt][1] = As[s][mb + 8][k0 + tcol];
                af[mt][2] = As[s][mb    ][k0 + tcol + 4];
                af[mt][3] = As[s][mb + 8][k0 + tcol + 4];
            }
            #pragma unroll
            for (int nt = 0; nt < 4; nt++) {
                const int nb = n0 + nt*8 + group;
                bf[nt][0] = Ws[s][k0 + tcol    ][nb];
                bf[nt][1] = Ws[s][k0 + tcol + 4][nb];
            }
            #pragma unroll
            for (int mt = 0; mt < 4; mt++)
                #pragma unroll
                for (int nt = 0; nt < 4; nt++)
                    mma_tf32(c[mt][nt], af[mt], bf[nt]);
        }

        // ---- stage next tile ----
        if (more) {
            const int s2 = s ^ 1;
            #pragma unroll
            for (int i = 0; i < 4; i++) {
                uint32_t* p = &As[s2][aRow + i*32][aCol];
                p[0]=f2tf(pa[i].x); p[1]=f2tf(pa[i].y); p[2]=f2tf(pa[i].z); p[3]=f2tf(pa[i].w);
            }
            #pragma unroll
            for (int i = 0; i < 4; i++) {
                uint32_t* p = &Ws[s2][wRow][wCol + i*32];
                p[0]=f2tf(pw[i].x); p[1]=f2tf(pw[i].y); p[2]=f2tf(pw[i].z); p[3]=f2tf(pw[i].w);
            }
        }
        s ^= 1;
    }

    // ---- epilogue ----
    #pragma unroll
    for (int mt = 0; mt < 4; mt++) {
        #pragma unroll
        for (int nt = 0; nt < 4; nt++) {
            const int col = bx*128 + n0 + nt*8 + tcol*2;
            float2 bb = *(const float2*)&bias[col];
            #pragma unroll
            for (int r = 0; r < 2; r++) {
                const int row = by*128 + m0 + mt*16 + group + r*8;
                float2 v;
                v.x = c[mt][nt][r*2+0] + bb.x;
                v.y = c[mt][nt][r*2+1] + bb.y;
                if (RELU) { v.x = fmaxf(v.x, 0.f); v.y = fmaxf(v.y, 0.f); }
                float2* cp = (float2*)&C[(size_t)row*N + col];
                if (RES) { float2 o = *cp; v.x += o.x; v.y += o.y; }
                *cp = v;
            }
        }
    }
}

template<bool RELU, bool RES>
__global__ __launch_bounds__(256) void gemm128(
    int M, int N, int K,
    const float* __restrict__ A,
    const float* __restrict__ W,
    const float* __restrict__ bias,
    float* __restrict__ C)
{
    extern __shared__ uint32_t dsm[];
    gemm_core<RELU,RES>(A, W, bias, C, M, N, K, blockIdx.x, blockIdx.y, dsm);
}

// fused QKV: grid.x = 12 (3 weights x 4 N-tiles of 128), grid.y = M/128
__global__ __launch_bounds__(256) void qkv_gemm(
    const float* __restrict__ A,
    const float* __restrict__ Wq, const float* __restrict__ Wk, const float* __restrict__ Wv,
    const float* __restrict__ bq, const float* __restrict__ bk, const float* __restrict__ bv,
    float* __restrict__ q, float* __restrict__ k, float* __restrict__ v)
{
    extern __shared__ uint32_t dsm[];
    const int w   = blockIdx.x >> 2;
    const int nbx = blockIdx.x & 3;
    const float* W = (w == 0) ? Wq : (w == 1) ? Wk : Wv;
    const float* b = (w == 0) ? bq : (w == 1) ? bk : bv;
    float*       C = (w == 0) ? q  : (w == 1) ? k  : v;
    gemm_core<false,false>(A, W, b, C, BT, EMB, EMB, nbx, blockIdx.y, dsm);
}

// ---------------- flash attention (unchanged, known-good) ----------------
__global__ __launch_bounds__(128) void attn_flash_kernel(
        const float* __restrict__ Q,
        const float* __restrict__ K,
        const float* __restrict__ V,
        float* __restrict__ O)
{
    const int qt = blockIdx.x;
    const int h  = blockIdx.y;
    const int b  = blockIdx.z;
    const int tid = threadIdx.x;
    const int ty = tid >> 3;     // 0..15
    const int tx = tid & 7;      // 0..7

    __shared__ float Qs[64][68];
    __shared__ float Ks[64][36];
    __shared__ float Vs[32][68];
    __shared__ float Ps[64][36];

    const size_t base = ((size_t)b*SEQ)*EMB + (size_t)h*HEADD;

    for (int idx = tid; idx < 64*16; idx += 128) {
        int q  = idx >> 4;
        int d4 = (idx & 15) << 2;
        float4 v = *(const float4*)&Q[base + (size_t)(qt*64 + q)*EMB + d4];
        Qs[d4+0][q] = v.x * 0.125f;
        Qs[d4+1][q] = v.y * 0.125f;
        Qs[d4+2][q] = v.z * 0.125f;
        Qs[d4+3][q] = v.w * 0.125f;
    }

    float m[4], l[4], o[4][8];
    #pragma unroll
    for (int i = 0; i < 4; i++) {
        m[i] = -1e30f; l[i] = 0.f;
        #pragma unroll
        for (int j = 0; j < 8; j++) o[i][j] = 0.f;
    }

    const int nkt = 2*qt + 2;
    for (int kt = 0; kt < nkt; kt++) {
        __syncthreads();

        for (int idx = tid; idx < 32*16; idx += 128) {
            int k  = idx >> 4;
            int d4 = (idx & 15) << 2;
            float4 kv = *(const float4*)&K[base + (size_t)(kt*32 + k)*EMB + d4];
            Ks[d4+0][k] = kv.x; Ks[d4+1][k] = kv.y;
            Ks[d4+2][k] = kv.z; Ks[d4+3][k] = kv.w;
            *(float4*)&Vs[k][d4] =
                *(const float4*)&V[base + (size_t)(kt*32 + k)*EMB + d4];
        }
        __syncthreads();

        float acc[4][4];
        #pragma unroll
        for (int i = 0; i < 4; i++)
            #pragma unroll
            for (int j = 0; j < 4; j++) acc[i][j] = 0.f;

        #pragma unroll 8
        for (int d = 0; d < 64; d++) {
            float4 qv = *(const float4*)&Qs[d][ty*4];
            float4 kv = *(const float4*)&Ks[d][tx*4];
            acc[0][0] += qv.x*kv.x; acc[0][1] += qv.x*kv.y; acc[0][2] += qv.x*kv.z; acc[0][3] += qv.x*kv.w;
            acc[1][0] += qv.y*kv.x; acc[1][1] += qv.y*kv.y; acc[1][2] += qv.y*kv.z; acc[1][3] += qv.y*kv.w;
            acc[2][0] += qv.z*kv.x; acc[2][1] += qv.z*kv.y; acc[2][2] += qv.z*kv.z; acc[2][3] += qv.z*kv.w;
            acc[3][0] += qv.w*kv.x; acc[3][1] += qv.w*kv.y; acc[3][2] += qv.w*kv.z; acc[3][3] += qv.w*kv.w;
        }

        if (kt >= 2*qt) {
            #pragma unroll
            for (int i = 0; i < 4; i++) {
                int qg = qt*64 + ty*4 + i;
                #pragma unroll
                for (int j = 0; j < 4; j++) {
                    int kg = kt*32 + tx*4 + j;
                    if (kg > qg) acc[i][j] = -1e30f;
                }
            }
        }

        #pragma unroll
        for (int i = 0; i < 4; i++) {
            float rmax = fmaxf(fmaxf(acc[i][0], acc[i][1]), fmaxf(acc[i][2], acc[i][3]));
            rmax = fmaxf(rmax, __shfl_xor_sync(0xffffffffu, rmax, 1));
            rmax = fmaxf(rmax, __shfl_xor_sync(0xffffffffu, rmax, 2));
            rmax = fmaxf(rmax, __shfl_xor_sync(0xffffffffu, rmax, 4));
            float mn = fmaxf(m[i], rmax);
            float cc = __expf(m[i] - mn);
            m[i] = mn;
            l[i] *= cc;
            #pragma unroll
            for (int j = 0; j < 8; j++) o[i][j] *= cc;
            float ps = 0.f;
            #pragma unroll
            for (int j = 0; j < 4; j++) {
                float p = __expf(acc[i][j] - mn);
                Ps[ty*4+i][tx*4+j] = p;
                ps += p;
            }
            ps += __shfl_xor_sync(0xffffffffu, ps, 1);
            ps += __shfl_xor_sync(0xffffffffu, ps, 2);
            ps += __shfl_xor_sync(0xffffffffu, ps, 4);
            l[i] += ps;
        }
        __syncthreads();

        for (int k = 0; k < 32; k += 4) {
            float p[4][4];
            #pragma unroll
            for (int i = 0; i < 4; i++)
                *(float4*)p[i] = *(const float4*)&Ps[ty*4+i][k];
            #pragma unroll
            for (int kk = 0; kk < 4; kk++) {
                float4 v0 = *(const float4*)&Vs[k+kk][tx*8];
                float4 v1 = *(const float4*)&Vs[k+kk][tx*8+4];
                #pragma unroll
                for (int i = 0; i < 4; i++) {
                    float pv = p[i][kk];
                    o[i][0] += pv*v0.x; o[i][1] += pv*v0.y;
                    o[i][2] += pv*v0.z; o[i][3] += pv*v0.w;
                    o[i][4] += pv*v1.x; o[i][5] += pv*v1.y;
                    o[i][6] += pv*v1.z; o[i][7] += pv*v1.w;
                }
            }
        }
    }

    #pragma unroll
    for (int i = 0; i < 4; i++) {
        float inv = 1.0f / l[i];
        int qg = qt*64 + ty*4 + i;
        float4 r0, r1;
        r0.x = o[i][0]*inv; r0.y = o[i][1]*inv; r0.z = o[i][2]*inv; r0.w = o[i][3]*inv;
        r1.x = o[i][4]*inv; r1.y = o[i][5]*inv; r1.z = o[i][6]*inv; r1.w = o[i][7]*inv;
        float* op = &O[base + (size_t)qg*EMB + tx*8];
        *(float4*)op       = r0;
        *(float4*)(op + 4) = r1;
    }
}

// ---------------- orchestration ----------------
extern "C" void kernel_launch(void* const* d_in, const int* in_sizes, int n_in,
                              void* d_out, int out_size)
{
    (void)in_sizes; (void)n_in;
    const int*   x       = (const int*)  d_in[0];
    const float* tok_emb = (const float*)d_in[1];
    const float* pos_emb = (const float*)d_in[2];
    const float* Wq   = (const float*)d_in[3];
    const float* bq   = (const float*)d_in[4];
    const float* Wk   = (const float*)d_in[5];
    const float* bk   = (const float*)d_in[6];
    const float* Wv   = (const float*)d_in[7];
    const float* bv   = (const float*)d_in[8];
    const float* Wo   = (const float*)d_in[9];
    const float* bo   = (const float*)d_in[10];
    const float* ln1s = (const float*)d_in[11];
    const float* ln1b = (const float*)d_in[12];
    const float* ln2s = (const float*)d_in[13];
    const float* ln2b = (const float*)d_in[14];
    const float* W1   = (const float*)d_in[15];
    const float* b1   = (const float*)d_in[16];
    const float* W2   = (const float*)d_in[17];
    const float* b2   = (const float*)d_in[18];
    const float* Wout = (const float*)d_in[19];
    const float* bout = (const float*)d_in[20];
    float* out = (float*)d_out;
    (void)out_size;

    float *h, *y, *q, *k, *v, *o, *ff;
    cudaGetSymbolAddress((void**)&h,  g_h);
    cudaGetSymbolAddress((void**)&y,  g_y);
    cudaGetSymbolAddress((void**)&q,  g_q);
    cudaGetSymbolAddress((void**)&k,  g_k);
    cudaGetSymbolAddress((void**)&v,  g_v);
    cudaGetSymbolAddress((void**)&o,  g_o);
    cudaGetSymbolAddress((void**)&ff, g_ff);

    cudaFuncSetAttribute(gemm128<false,false>,
        cudaFuncAttributeMaxDynamicSharedMemorySize, GEMM_SMEM_BYTES);
    cudaFuncSetAttribute(gemm128<false,true>,
        cudaFuncAttributeMaxDynamicSharedMemorySize, GEMM_SMEM_BYTES);
    cudaFuncSetAttribute(gemm128<true,false>,
        cudaFuncAttributeMaxDynamicSharedMemorySize, GEMM_SMEM_BYTES);
    cudaFuncSetAttribute(qkv_gemm,
        cudaFuncAttributeMaxDynamicSharedMemorySize, GEMM_SMEM_BYTES);

    const int M = BT;
    embed_kernel<<<BT, 128>>>(x, tok_emb, pos_emb, h);

    for (int i = 0; i < NLAYER; i++) {
        const float* Wqi = Wq + (size_t)i*EMB*EMB;
        const float* Wki = Wk + (size_t)i*EMB*EMB;
        const float* Wvi = Wv + (size_t)i*EMB*EMB;
        const float* Woi = Wo + (size_t)i*EMB*EMB;
        const float* W1i = W1 + (size_t)i*EMB*FFDIM;
        const float* W2i = W2 + (size_t)i*FFDIM*EMB;

        ln_kernel<<<BT, 128>>>(h, ln1s + i*EMB, ln1b + i*EMB, y);

        qkv_gemm<<<dim3(12, M/128), 256, GEMM_SMEM_BYTES>>>(
            y, Wqi, Wki, Wvi, bq + i*EMB, bk + i*EMB, bv + i*EMB, q, k, v);

        attn_flash_kernel<<<dim3(SEQ/64, NHEAD, BATCH), 128>>>(q, k, v, o);

        gemm128<false,true><<<dim3(EMB/128, M/128), 256, GEMM_SMEM_BYTES>>>(
            M, EMB, EMB, o, Woi, bo + i*EMB, h);

        ln_kernel<<<BT, 128>>>(h, ln2s + i*EMB, ln2b + i*EMB, y);

        gemm128<true,false><<<dim3(FFDIM/128, M/128), 256, GEMM_SMEM_BYTES>>>(
            M, FFDIM, EMB, y, W1i, b1 + i*FFDIM, ff);

        gemm128<false,true><<<dim3(EMB/128, M/128), 256, GEMM_SMEM_BYTES>>>(
            M, EMB, FFDIM, ff, W2i, b2 + i*EMB, h);
    }

    gemm128<false,false><<<dim3(VOCAB/128, M/128), 256, GEMM_SMEM_BYTES>>>(
        M, VOCAB, EMB, h, Wout, bout, out);
}

// round 5
// speedup vs baseline: 15.4729x; 1.6068x over previous
#include <cuda_runtime.h>
#include <cuda_bf16.h>
#include <math.h>
#include <stdint.h>

// ---------------- problem constants ----------------
#define VOCAB 32000
#define EMB   512
#define SEQ   2048
#define NHEAD 8
#define NLAYER 6
#define FFDIM 2048
#define BATCH 2
#define HEADD 64
#define BT    (BATCH*SEQ)      // 4096 tokens
#define EPS_LN 1e-5f

// ---------------- scratch (device globals; no allocation allowed) ----------------
__device__ float g_h [BT*EMB];
__device__ float g_y [BT*EMB];
__device__ float g_q [BT*EMB];
__device__ float g_k [BT*EMB];
__device__ float g_v [BT*EMB];
__device__ float g_o [BT*EMB];
__device__ float g_ff[BT*FFDIM];

// ---------------- embedding ----------------
__global__ void embed_kernel(const int* __restrict__ x,
                             const float* __restrict__ tok,
                             const float* __restrict__ pos,
                             float* __restrict__ h)
{
    int row = blockIdx.x;
    int t   = row % SEQ;
    int id  = x[row];
    const float* te = tok + (size_t)id * EMB;
    const float* pe = pos + (size_t)t  * EMB;
    float* out = h + (size_t)row * EMB;
    for (int i = threadIdx.x; i < EMB; i += blockDim.x)
        out[i] = te[i] + pe[i];
}

// ---------------- layernorm ----------------
__global__ void ln_kernel(const float* __restrict__ X,
                          const float* __restrict__ scale,
                          const float* __restrict__ bias,
                          float* __restrict__ Y)
{
    int row = blockIdx.x;
    int t = threadIdx.x;                   // 128 threads
    const float* x = X + (size_t)row * EMB;
    float* y = Y + (size_t)row * EMB;

    float s = 0.f, sq = 0.f;
    #pragma unroll
    for (int i = t; i < EMB; i += 128) { float v = x[i]; s += v; sq += v*v; }

    __shared__ float r1[128], r2[128];
    r1[t] = s; r2[t] = sq;
    __syncthreads();
    for (int k = 64; k > 0; k >>= 1) {
        if (t < k) { r1[t] += r1[t+k]; r2[t] += r2[t+k]; }
        __syncthreads();
    }
    float mean = r1[0] * (1.0f/EMB);
    float var  = r2[0] * (1.0f/EMB) - mean*mean;
    float rstd = rsqrtf(var + EPS_LN);

    #pragma unroll
    for (int i = t; i < EMB; i += 128)
        y[i] = (x[i] - mean) * rstd * scale[i] + bias[i];
}

// ---------------- tf32 helpers ----------------
__device__ __forceinline__ uint32_t f2tf(float f) {
    uint32_t u; asm("cvt.rna.tf32.f32 %0, %1;" : "=r"(u) : "f"(f)); return u;
}

__device__ __forceinline__ void mma_tf32(float* c, const uint32_t* a, const uint32_t* b) {
    asm volatile(
        "mma.sync.aligned.m16n8k8.row.col.f32.tf32.tf32.f32 "
        "{%0,%1,%2,%3}, {%4,%5,%6,%7}, {%8,%9}, {%0,%1,%2,%3};\n"
        : "+f"(c[0]), "+f"(c[1]), "+f"(c[2]), "+f"(c[3])
        : "r"(a[0]), "r"(a[1]), "r"(a[2]), "r"(a[3]),
          "r"(b[0]), "r"(b[1]));
}

// ---------------- tf32 tensor-core GEMM core ----------------
// Block tile 128x128x32, 256 threads = 8 warps (2 along M x 4 along N),
// warp tile 64x32 = 4x4 m16n8k8 tiles. Double-buffered smem.
#define APAD 36    // A row stride: frag banks (4g+t)%32 distinct
#define WPAD 136   // W row stride: mod32=8 -> frag banks (8t+g)%32 distinct
#define GEMM_SMEM_BYTES ((2*128*APAD + 2*32*WPAD)*4)   // 71680 B

template<bool RELU, bool RES>
__device__ __forceinline__ void gemm_core(
    const float* __restrict__ A,
    const float* __restrict__ W,
    const float* __restrict__ bias,
    float* __restrict__ C,
    int M, int N, int K, int bx, int by, uint32_t* dsm)
{
    uint32_t (*As)[128][APAD] = (uint32_t(*)[128][APAD])dsm;
    uint32_t (*Ws)[32][WPAD]  = (uint32_t(*)[32][WPAD])(dsm + 2*128*APAD);

    const int tid  = threadIdx.x;
    const int warp = tid >> 5, lane = tid & 31;
    const int m0   = (warp & 1) * 64;
    const int n0   = (warp >> 1) * 32;
    const int group = lane >> 2, tcol = lane & 3;

    const int aRow = tid >> 3;
    const int aCol = (tid & 7) << 2;
    const int wRow = tid >> 3;
    const int wCol = (tid & 7) << 2;

    float c[4][4][4];
    #pragma unroll
    for (int mt = 0; mt < 4; mt++)
        #pragma unroll
        for (int nt = 0; nt < 4; nt++)
            #pragma unroll
            for (int j = 0; j < 4; j++) c[mt][nt][j] = 0.f;

    const int ktiles = K >> 5;
    float4 pa[4], pw[4];

    #pragma unroll
    for (int i = 0; i < 4; i++)
        pa[i] = *(const float4*)&A[(size_t)(by*128 + aRow + i*32)*K + aCol];
    #pragma unroll
    for (int i = 0; i < 4; i++)
        pw[i] = *(const float4*)&W[(size_t)wRow*N + bx*128 + wCol + i*32];

    #pragma unroll
    for (int i = 0; i < 4; i++) {
        uint32_t* p = &As[0][aRow + i*32][aCol];
        p[0]=f2tf(pa[i].x); p[1]=f2tf(pa[i].y); p[2]=f2tf(pa[i].z); p[3]=f2tf(pa[i].w);
    }
    #pragma unroll
    for (int i = 0; i < 4; i++) {
        uint32_t* p = &Ws[0][wRow][wCol + i*32];
        p[0]=f2tf(pw[i].x); p[1]=f2tf(pw[i].y); p[2]=f2tf(pw[i].z); p[3]=f2tf(pw[i].w);
    }

    int s = 0;
    for (int kt = 0; kt < ktiles; kt++) {
        __syncthreads();

        const bool more = (kt + 1 < ktiles);
        if (more) {
            const int kb = (kt + 1) << 5;
            #pragma unroll
            for (int i = 0; i < 4; i++)
                pa[i] = *(const float4*)&A[(size_t)(by*128 + aRow + i*32)*K + kb + aCol];
            #pragma unroll
            for (int i = 0; i < 4; i++)
                pw[i] = *(const float4*)&W[(size_t)(kb + wRow)*N + bx*128 + wCol + i*32];
        }

        #pragma unroll
        for (int ks = 0; ks < 4; ks++) {
            const int k0 = ks << 3;
            uint32_t af[4][4], bf[4][2];
            #pragma unroll
            for (int mt = 0; mt < 4; mt++) {
                const int mb = m0 + mt*16 + group;
                af[mt][0] = As[s][mb    ][k0 + tcol];
                af[mt][1] = As[s][mb + 8][k0 + tcol];
                af[mt][2] = As[s][mb    ][k0 + tcol + 4];
                af[mt][3] = As[s][mb + 8][k0 + tcol + 4];
            }
            #pragma unroll
            for (int nt = 0; nt < 4; nt++) {
                const int nb = n0 + nt*8 + group;
                bf[nt][0] = Ws[s][k0 + tcol    ][nb];
                bf[nt][1] = Ws[s][k0 + tcol + 4][nb];
            }
            #pragma unroll
            for (int mt = 0; mt < 4; mt++)
                #pragma unroll
                for (int nt = 0; nt < 4; nt++)
                    mma_tf32(c[mt][nt], af[mt], bf[nt]);
        }

        if (more) {
            const int s2 = s ^ 1;
            #pragma unroll
            for (int i = 0; i < 4; i++) {
                uint32_t* p = &As[s2][aRow + i*32][aCol];
                p[0]=f2tf(pa[i].x); p[1]=f2tf(pa[i].y); p[2]=f2tf(pa[i].z); p[3]=f2tf(pa[i].w);
            }
            #pragma unroll
            for (int i = 0; i < 4; i++) {
                uint32_t* p = &Ws[s2][wRow][wCol + i*32];
                p[0]=f2tf(pw[i].x); p[1]=f2tf(pw[i].y); p[2]=f2tf(pw[i].z); p[3]=f2tf(pw[i].w);
            }
        }
        s ^= 1;
    }

    #pragma unroll
    for (int mt = 0; mt < 4; mt++) {
        #pragma unroll
        for (int nt = 0; nt < 4; nt++) {
            const int col = bx*128 + n0 + nt*8 + tcol*2;
            float2 bb = *(const float2*)&bias[col];
            #pragma unroll
            for (int r = 0; r < 2; r++) {
                const int row = by*128 + m0 + mt*16 + group + r*8;
                float2 v;
                v.x = c[mt][nt][r*2+0] + bb.x;
                v.y = c[mt][nt][r*2+1] + bb.y;
                if (RELU) { v.x = fmaxf(v.x, 0.f); v.y = fmaxf(v.y, 0.f); }
                float2* cp = (float2*)&C[(size_t)row*N + col];
                if (RES) { float2 o = *cp; v.x += o.x; v.y += o.y; }
                *cp = v;
            }
        }
    }
}

template<bool RELU, bool RES>
__global__ __launch_bounds__(256) void gemm128(
    int M, int N, int K,
    const float* __restrict__ A,
    const float* __restrict__ W,
    const float* __restrict__ bias,
    float* __restrict__ C)
{
    extern __shared__ uint32_t dsm[];
    gemm_core<RELU,RES>(A, W, bias, C, M, N, K, blockIdx.x, blockIdx.y, dsm);
}

__global__ __launch_bounds__(256) void qkv_gemm(
    const float* __restrict__ A,
    const float* __restrict__ Wq, const float* __restrict__ Wk, const float* __restrict__ Wv,
    const float* __restrict__ bq, const float* __restrict__ bk, const float* __restrict__ bv,
    float* __restrict__ q, float* __restrict__ k, float* __restrict__ v)
{
    extern __shared__ uint32_t dsm[];
    const int w   = blockIdx.x >> 2;
    const int nbx = blockIdx.x & 3;
    const float* W = (w == 0) ? Wq : (w == 1) ? Wk : Wv;
    const float* b = (w == 0) ? bq : (w == 1) ? bk : bv;
    float*       C = (w == 0) ? q  : (w == 1) ? k  : v;
    gemm_core<false,false>(A, W, b, C, BT, EMB, EMB, nbx, blockIdx.y, dsm);
}

// ---------------- tensor-core flash attention ----------------
// 128 queries/CTA, 8 warps x 16 q-rows, 64-key tiles.
// All smem in NATURAL [token][dim] layout; strides chosen so mma fragment
// reads are bank-conflict-free (Qs/Ks/Ps stride 68 -> 4g+t; Vs stride 72 -> 8t+g).
// Q fragments live in registers; Qs staging buffer is reused as the P buffer.
#define QS_STRIDE 68
#define KS_STRIDE 68
#define VS_STRIDE 72
#define PS_STRIDE 68
#define ATT_SMEM_WORDS (128*QS_STRIDE + 64*KS_STRIDE + 64*VS_STRIDE)
#define ATT_SMEM_BYTES (ATT_SMEM_WORDS*4)   // 104,192 B... (qs reused as ps)

__global__ __launch_bounds__(256, 2) void attn_mma_kernel(
        const float* __restrict__ Q,
        const float* __restrict__ K,
        const float* __restrict__ V,
        float* __restrict__ O)
{
    extern __shared__ uint32_t sm[];
    uint32_t* qs = sm;                          // 128 x QS_STRIDE (reused as ps)
    uint32_t* ks = qs + 128*QS_STRIDE;          // 64 x KS_STRIDE
    uint32_t* vs = ks + 64*KS_STRIDE;           // 64 x VS_STRIDE
    uint32_t* ps = qs;                          // alias: Q frags are in regs by then

    const int bq = blockIdx.x, hh = blockIdx.y, bb = blockIdx.z;
    const int tid = threadIdx.x, warp = tid >> 5, lane = tid & 31;
    const int g = lane >> 2, tc = lane & 3;
    const int wq = warp * 16;

    const size_t base = ((size_t)bb*SEQ)*EMB + (size_t)hh*HEADD;

    // ---- stage Q (scaled by 1/8, tf32), coalesced ----
    #pragma unroll
    for (int i = 0; i < 8; i++) {
        int f   = i*256 + tid;
        int row = f >> 4, d4 = (f & 15) << 2;
        float4 v = *(const float4*)&Q[base + (size_t)(bq*128 + row)*EMB + d4];
        uint4 u = { f2tf(v.x*0.125f), f2tf(v.y*0.125f), f2tf(v.z*0.125f), f2tf(v.w*0.125f) };
        *(uint4*)&qs[row*QS_STRIDE + d4] = u;
    }
    __syncthreads();

    // ---- Q fragments to registers (held for entire kernel) ----
    uint32_t qf[8][4];
    #pragma unroll
    for (int ki = 0; ki < 8; ki++) {
        int k0 = ki*8;
        qf[ki][0] = qs[(wq+g  )*QS_STRIDE + k0 + tc];
        qf[ki][1] = qs[(wq+g+8)*QS_STRIDE + k0 + tc];
        qf[ki][2] = qs[(wq+g  )*QS_STRIDE + k0 + tc + 4];
        qf[ki][3] = qs[(wq+g+8)*QS_STRIDE + k0 + tc + 4];
    }

    float o[8][4];
    #pragma unroll
    for (int nt = 0; nt < 8; nt++)
        #pragma unroll
        for (int j = 0; j < 4; j++) o[nt][j] = 0.f;
    float m0 = -1e30f, m1 = -1e30f, l0 = 0.f, l1 = 0.f;

    const int nkt = 2*bq + 2;
    for (int kt = 0; kt < nkt; kt++) {
        __syncthreads();   // prev-tile consumers done (incl. ps alias of qs on kt=0)

        // ---- load K, V tiles (natural layout, coalesced, tf32) ----
        #pragma unroll
        for (int i = 0; i < 4; i++) {
            int f   = i*256 + tid;
            int tok = f >> 4, d4 = (f & 15) << 2;
            float4 kv = *(const float4*)&K[base + (size_t)(kt*64 + tok)*EMB + d4];
            uint4 uk = { f2tf(kv.x), f2tf(kv.y), f2tf(kv.z), f2tf(kv.w) };
            *(uint4*)&ks[tok*KS_STRIDE + d4] = uk;
            float4 vv = *(const float4*)&V[base + (size_t)(kt*64 + tok)*EMB + d4];
            uint4 uv = { f2tf(vv.x), f2tf(vv.y), f2tf(vv.z), f2tf(vv.w) };
            *(uint4*)&vs[tok*VS_STRIDE + d4] = uv;
        }
        __syncthreads();

        // ---- scores: sc[nt] = Q(16xd) x K^T; B[k=d][n=tok] = ks[tok][d] ----
        float sc[8][4];
        #pragma unroll
        for (int nt = 0; nt < 8; nt++)
            #pragma unroll
            for (int j = 0; j < 4; j++) sc[nt][j] = 0.f;

        #pragma unroll
        for (int ki = 0; ki < 8; ki++) {
            int k0 = ki*8;
            uint32_t bf[8][2];
            #pragma unroll
            for (int nt = 0; nt < 8; nt++) {
                int nb = nt*8 + g;
                bf[nt][0] = ks[nb*KS_STRIDE + k0 + tc];
                bf[nt][1] = ks[nb*KS_STRIDE + k0 + tc + 4];
            }
            #pragma unroll
            for (int nt = 0; nt < 8; nt++)
                mma_tf32(sc[nt], qf[ki], bf[nt]);
        }

        // ---- causal mask (only last two tiles can cross the diagonal) ----
        if (kt >= 2*bq) {
            const int row0 = bq*128 + wq + g;
            #pragma unroll
            for (int nt = 0; nt < 8; nt++) {
                int c0 = kt*64 + nt*8 + 2*tc;
                if (c0     > row0    ) sc[nt][0] = -1e30f;
                if (c0 + 1 > row0    ) sc[nt][1] = -1e30f;
                if (c0     > row0 + 8) sc[nt][2] = -1e30f;
                if (c0 + 1 > row0 + 8) sc[nt][3] = -1e30f;
            }
        }

        // ---- online softmax (rows r0=wq+g, r1=wq+g+8; quad shuffles) ----
        float r0 = -1e30f, r1 = -1e30f;
        #pragma unroll
        for (int nt = 0; nt < 8; nt++) {
            r0 = fmaxf(r0, fmaxf(sc[nt][0], sc[nt][1]));
            r1 = fmaxf(r1, fmaxf(sc[nt][2], sc[nt][3]));
        }
        r0 = fmaxf(r0, __shfl_xor_sync(0xffffffffu, r0, 1));
        r0 = fmaxf(r0, __shfl_xor_sync(0xffffffffu, r0, 2));
        r1 = fmaxf(r1, __shfl_xor_sync(0xffffffffu, r1, 1));
        r1 = fmaxf(r1, __shfl_xor_sync(0xffffffffu, r1, 2));

        float mn0 = fmaxf(m0, r0), mn1 = fmaxf(m1, r1);
        float cor0 = __expf(m0 - mn0), cor1 = __expf(m1 - mn1);
        m0 = mn0; m1 = mn1;
        l0 *= cor0; l1 *= cor1;
        #pragma unroll
        for (int nt = 0; nt < 8; nt++) {
            o[nt][0] *= cor0; o[nt][1] *= cor0;
            o[nt][2] *= cor1; o[nt][3] *= cor1;
        }

        float s0 = 0.f, s1 = 0.f;
        #pragma unroll
        for (int nt = 0; nt < 8; nt++) {
            float p00 = __expf(sc[nt][0] - mn0);
            float p01 = __expf(sc[nt][1] - mn0);
            float p10 = __expf(sc[nt][2] - mn1);
            float p11 = __expf(sc[nt][3] - mn1);
            s0 += p00 + p01; s1 += p10 + p11;
            int col = nt*8 + 2*tc;
            ps[(wq+g  )*PS_STRIDE + col    ] = f2tf(p00);
            ps[(wq+g  )*PS_STRIDE + col + 1] = f2tf(p01);
            ps[(wq+g+8)*PS_STRIDE + col    ] = f2tf(p10);
            ps[(wq+g+8)*PS_STRIDE + col + 1] = f2tf(p11);
        }
        s0 += __shfl_xor_sync(0xffffffffu, s0, 1);
        s0 += __shfl_xor_sync(0xffffffffu, s0, 2);
        s1 += __shfl_xor_sync(0xffffffffu, s1, 1);
        s1 += __shfl_xor_sync(0xffffffffu, s1, 2);
        l0 += s0; l1 += s1;
        __syncwarp();   // Ps region is per-warp private: warp-level sync suffices

        // ---- PV: o += P(16x64) x V(64xd); B[k=tok][n=d] = vs[tok][d] ----
        #pragma unroll
        for (int ki = 0; ki < 8; ki++) {
            int k0 = ki*8;
            uint32_t af[4];
            af[0] = ps[(wq+g  )*PS_STRIDE + k0 + tc];
            af[1] = ps[(wq+g+8)*PS_STRIDE + k0 + tc];
            af[2] = ps[(wq+g  )*PS_STRIDE + k0 + tc + 4];
            af[3] = ps[(wq+g+8)*PS_STRIDE + k0 + tc + 4];
            uint32_t bf[8][2];
            #pragma unroll
            for (int nt = 0; nt < 8; nt++) {
                int nb = nt*8 + g;
                bf[nt][0] = vs[(k0 + tc    )*VS_STRIDE + nb];
                bf[nt][1] = vs[(k0 + tc + 4)*VS_STRIDE + nb];
            }
            #pragma unroll
            for (int nt = 0; nt < 8; nt++)
                mma_tf32(o[nt], af, bf[nt]);
        }
        __syncwarp();
    }

    // ---- epilogue ----
    float inv0 = 1.0f / l0, inv1 = 1.0f / l1;
    const int row0 = bq*128 + wq + g;
    #pragma unroll
    for (int nt = 0; nt < 8; nt++) {
        int d = nt*8 + 2*tc;
        float2 a; a.x = o[nt][0]*inv0; a.y = o[nt][1]*inv0;
        *(float2*)&O[base + (size_t)row0*EMB + d] = a;
        float2 b; b.x = o[nt][2]*inv1; b.y = o[nt][3]*inv1;
        *(float2*)&O[base + (size_t)(row0+8)*EMB + d] = b;
    }
}

// ---------------- orchestration ----------------
extern "C" void kernel_launch(void* const* d_in, const int* in_sizes, int n_in,
                              void* d_out, int out_size)
{
    (void)in_sizes; (void)n_in;
    const int*   x       = (const int*)  d_in[0];
    const float* tok_emb = (const float*)d_in[1];
    const float* pos_emb = (const float*)d_in[2];
    const float* Wq   = (const float*)d_in[3];
    const float* bq   = (const float*)d_in[4];
    const float* Wk   = (const float*)d_in[5];
    const float* bk   = (const float*)d_in[6];
    const float* Wv   = (const float*)d_in[7];
    const float* bv   = (const float*)d_in[8];
    const float* Wo   = (const float*)d_in[9];
    const float* bo   = (const float*)d_in[10];
    const float* ln1s = (const float*)d_in[11];
    const float* ln1b = (const float*)d_in[12];
    const float* ln2s = (const float*)d_in[13];
    const float* ln2b = (const float*)d_in[14];
    const float* W1   = (const float*)d_in[15];
    const float* b1   = (const float*)d_in[16];
    const float* W2   = (const float*)d_in[17];
    const float* b2   = (const float*)d_in[18];
    const float* Wout = (const float*)d_in[19];
    const float* bout = (const float*)d_in[20];
    float* out = (float*)d_out;
    (void)out_size;

    float *h, *y, *q, *k, *v, *o, *ff;
    cudaGetSymbolAddress((void**)&h,  g_h);
    cudaGetSymbolAddress((void**)&y,  g_y);
    cudaGetSymbolAddress((void**)&q,  g_q);
    cudaGetSymbolAddress((void**)&k,  g_k);
    cudaGetSymbolAddress((void**)&v,  g_v);
    cudaGetSymbolAddress((void**)&o,  g_o);
    cudaGetSymbolAddress((void**)&ff, g_ff);

    cudaFuncSetAttribute(gemm128<false,false>,
        cudaFuncAttributeMaxDynamicSharedMemorySize, GEMM_SMEM_BYTES);
    cudaFuncSetAttribute(gemm128<false,true>,
        cudaFuncAttributeMaxDynamicSharedMemorySize, GEMM_SMEM_BYTES);
    cudaFuncSetAttribute(gemm128<true,false>,
        cudaFuncAttributeMaxDynamicSharedMemorySize, GEMM_SMEM_BYTES);
    cudaFuncSetAttribute(qkv_gemm,
        cudaFuncAttributeMaxDynamicSharedMemorySize, GEMM_SMEM_BYTES);
    cudaFuncSetAttribute(attn_mma_kernel,
        cudaFuncAttributeMaxDynamicSharedMemorySize, ATT_SMEM_BYTES);

    const int M = BT;
    embed_kernel<<<BT, 128>>>(x, tok_emb, pos_emb, h);

    for (int i = 0; i < NLAYER; i++) {
        const float* Wqi = Wq + (size_t)i*EMB*EMB;
        const float* Wki = Wk + (size_t)i*EMB*EMB;
        const float* Wvi = Wv + (size_t)i*EMB*EMB;
        const float* Woi = Wo + (size_t)i*EMB*EMB;
        const float* W1i = W1 + (size_t)i*EMB*FFDIM;
        const float* W2i = W2 + (size_t)i*FFDIM*EMB;

        ln_kernel<<<BT, 128>>>(h, ln1s + i*EMB, ln1b + i*EMB, y);

        qkv_gemm<<<dim3(12, M/128), 256, GEMM_SMEM_BYTES>>>(
            y, Wqi, Wki, Wvi, bq + i*EMB, bk + i*EMB, bv + i*EMB, q, k, v);

        attn_mma_kernel<<<dim3(SEQ/128, NHEAD, BATCH), 256, ATT_SMEM_BYTES>>>(q, k, v, o);

        gemm128<false,true><<<dim3(EMB/128, M/128), 256, GEMM_SMEM_BYTES>>>(
            M, EMB, EMB, o, Woi, bo + i*EMB, h);

        ln_kernel<<<BT, 128>>>(h, ln2s + i*EMB, ln2b + i*EMB, y);

        gemm128<true,false><<<dim3(FFDIM/128, M/128), 256, GEMM_SMEM_BYTES>>>(
            M, FFDIM, EMB, y, W1i, b1 + i*FFDIM, ff);

        gemm128<false,true><<<dim3(EMB/128, M/128), 256, GEMM_SMEM_BYTES>>>(
            M, EMB, FFDIM, ff, W2i, b2 + i*EMB, h);
    }

    gemm128<false,false><<<dim3(VOCAB/128, M/128), 256, GEMM_SMEM_BYTES>>>(
        M, VOCAB, EMB, h, Wout, bout, out);
}